// round 13
// baseline (speedup 1.0000x reference)
#include <cuda_runtime.h>
#include <cuda_fp16.h>
#include <math.h>
#include <stdint.h>

#define BB 4
#define TT 2048
#define DIN 513
#define TO 509
#define M2 (BB*TO)       /* 2036 */
#define DM 512
#define PROJD 4096
#define LL 5
#define DSTATE 64
#define DCONV 4
#define DI_ 1024
#define HH 16
#define CONVD_ 1152      /* DI + 2*DSTATE */
#define DINP 2192        /* 2*DI + 2*DSTATE + H */
#define EPSF 1e-5f

#define K3P_IN  1536     /* 3*512  */
#define K3P_W2  12288    /* 3*4096 */
#define K3P_OUT 6144     /* 3*2048 */
#define K3P_W1  21568    /* 3*7182=21546 padded to 32-mult */

// -------------------- scratch (device globals; no runtime alloc) ------------
__device__ float g_h0[(size_t)BB*TT*DIN];
__device__ float g_h [(size_t)M2*DM];
__device__ float g_zx[(size_t)2*M2*DINP];
__device__ float g_xbc[(size_t)2*M2*CONVD_];
__device__ float g_y [(size_t)2*M2*DI_];
__device__ __align__(16) __half g_a3[(size_t)BB*TO*K3P_W1];   // 43.9M
__device__ __align__(16) __half g_w3[(size_t)PROJD*K3P_W1];   // 88.3M
__device__ __align__(16) __half g_s3[(size_t)M2*K3P_W2];      // 25.0M (w1->w2 split)

__device__ __forceinline__ uint32_t smem_u32(const void* p) {
    uint32_t a;
    asm("{ .reg .u64 t; cvta.to.shared.u64 t, %1; cvt.u32.u64 %0, t; }"
        : "=r"(a) : "l"(p));
    return a;
}

// fp16 2-term split: hi+lo captures ~24 mantissa bits (fp32-class)
__device__ __forceinline__ void split3(float v, __half& hi, __half& lo) {
    hi = __float2half_rn(v);
    lo = __float2half_rn(v - __half2float(hi));
}

// ==================== mma.sync fp16 GEMM, 3-stage cp.async pipeline =========
// C = A3[M,K3] @ W3[N,K3]^T  (K3 % 32 == 0). 256 threads.
// OSPLIT=1: output written as fp16 [hi,lo,hi] triples (ldc = split elems/row).
#define SPITCH 40   /* halfs per smem row (32 data + 8 pad) = 80 bytes */
#define STAGES 3

template<int BN, int ACT, int ACCUM, int OSPLIT>
__global__ __launch_bounds__(256)
void mma_gemm(const __half* __restrict__ A, const __half* __restrict__ W,
              const float* __restrict__ bias, void* __restrict__ Cv,
              int M, int N, int K3, int ldc, long sA, long sW, long sC)
{
    constexpr int NN = BN / 16;
    constexpr int NB = BN / 32;
    constexpr int LB = BN / 64;
    constexpr int ABYTES = 128 * SPITCH * 2;
    constexpr int BBYTES = BN  * SPITCH * 2;

    extern __shared__ __align__(16) char dsm[];
    uint32_t asb = smem_u32(dsm);
    uint32_t bsb = asb + STAGES * ABYTES;

    int tid = threadIdx.x;
    int wid = tid >> 5, lane = tid & 31;
    int z = blockIdx.z;
    A += (long)z * sA;  W += (long)z * sW;
    int row0 = blockIdx.y * 128, col0 = blockIdx.x * BN;
    int wm = wid & 3, wn = wid >> 2;

    float acc[2][NN][4];
#pragma unroll
    for (int i = 0; i < 2; i++)
#pragma unroll
        for (int j = 0; j < NN; j++)
#pragma unroll
            for (int q = 0; q < 4; q++) acc[i][j][q] = 0.f;

    auto loadStage = [&](int ch, int s) {
        int k0 = ch << 5;
        uint32_t sa = asb + s * ABYTES;
#pragma unroll
        for (int l = 0; l < 2; l++) {
            int idx = tid + l * 256;
            int r = idx >> 2, c = idx & 3;
            int gr = row0 + r;
            int grc = gr < M ? gr : M - 1;
            const __half* src = A + (long)grc * K3 + k0 + c * 8;
            uint32_t dst = sa + (uint32_t)(r * (SPITCH * 2) + c * 16);
            int bytes = (gr < M) ? 16 : 0;
            asm volatile("cp.async.cg.shared.global [%0], [%1], 16, %2;"
                :: "r"(dst), "l"(src), "r"(bytes));
        }
        uint32_t sb2 = bsb + s * BBYTES;
#pragma unroll
        for (int l = 0; l < LB; l++) {
            int idx = tid + l * 256;
            int r = idx >> 2, c = idx & 3;
            int gn = col0 + r;
            int gnc = gn < N ? gn : N - 1;
            const __half* src = W + (long)gnc * K3 + k0 + c * 8;
            uint32_t dst = sb2 + (uint32_t)(r * (SPITCH * 2) + c * 16);
            int bytes = (gn < N) ? 16 : 0;
            asm volatile("cp.async.cg.shared.global [%0], [%1], 16, %2;"
                :: "r"(dst), "l"(src), "r"(bytes));
        }
        asm volatile("cp.async.commit_group;" ::: "memory");
    };

    auto compute = [&](int s) {
        uint32_t a_base = asb + s * ABYTES
            + (uint32_t)((wm * 32 + (lane & 15)) * 80 + (lane >> 4) * 16);
        uint32_t b_base = bsb + s * BBYTES
            + (uint32_t)((wn * (BN / 2) + ((lane >> 4) & 1) * 8 + (lane & 7)) * 80
                         + ((lane >> 3) & 1) * 16);
#pragma unroll
        for (int ks = 0; ks < 2; ks++) {
            uint32_t a[2][4];
#pragma unroll
            for (int mm = 0; mm < 2; mm++) {
                uint32_t ad = a_base + (uint32_t)(mm * 16 * 80 + ks * 32);
                asm volatile("ldmatrix.sync.aligned.m8n8.x4.shared.b16 {%0,%1,%2,%3}, [%4];"
                    : "=r"(a[mm][0]), "=r"(a[mm][1]), "=r"(a[mm][2]), "=r"(a[mm][3])
                    : "r"(ad));
            }
            uint32_t b[NB][4];
#pragma unroll
            for (int nb = 0; nb < NB; nb++) {
                uint32_t bd = b_base + (uint32_t)(nb * 16 * 80 + ks * 32);
                asm volatile("ldmatrix.sync.aligned.m8n8.x4.shared.b16 {%0,%1,%2,%3}, [%4];"
                    : "=r"(b[nb][0]), "=r"(b[nb][1]), "=r"(b[nb][2]), "=r"(b[nb][3])
                    : "r"(bd));
            }
#pragma unroll
            for (int mm = 0; mm < 2; mm++)
#pragma unroll
                for (int nn = 0; nn < NN; nn++) {
                    uint32_t b0 = b[nn >> 1][(nn & 1) * 2];
                    uint32_t b1 = b[nn >> 1][(nn & 1) * 2 + 1];
                    asm volatile(
                        "mma.sync.aligned.m16n8k16.row.col.f32.f16.f16.f32 "
                        "{%0,%1,%2,%3}, {%4,%5,%6,%7}, {%8,%9}, {%0,%1,%2,%3};"
                        : "+f"(acc[mm][nn][0]), "+f"(acc[mm][nn][1]),
                          "+f"(acc[mm][nn][2]), "+f"(acc[mm][nn][3])
                        : "r"(a[mm][0]), "r"(a[mm][1]), "r"(a[mm][2]), "r"(a[mm][3]),
                          "r"(b0), "r"(b1));
                }
        }
    };

    int NC = K3 >> 5;
    loadStage(0, 0);
    loadStage(1, 1);
    for (int ch = 0; ch < NC; ch++) {
        // RACE FIX: at the final chunk only ONE group is pending, so
        // wait_group 1 would return without its data landing. Drain fully.
        if (ch + 1 < NC)
            asm volatile("cp.async.wait_group 1;" ::: "memory");
        else
            asm volatile("cp.async.wait_group 0;" ::: "memory");
        __syncthreads();
        compute(ch % 3);
        int nx = ch + 2;
        if (nx < NC) loadStage(nx, nx % 3);
    }

    float* Cf = (float*)Cv + (OSPLIT ? 0 : (long)z * sC);
    __half* Cb = (__half*)Cv + (OSPLIT ? (long)z * sC : 0);

    int g = lane >> 2, t = lane & 3;
#pragma unroll
    for (int mm = 0; mm < 2; mm++) {
#pragma unroll
        for (int half_ = 0; half_ < 2; half_++) {
            int gr = row0 + wm * 32 + mm * 16 + g + half_ * 8;
            if (gr >= M) continue;
#pragma unroll
            for (int nn = 0; nn < NN; nn++) {
                int gn = col0 + wn * (BN / 2) + nn * 8 + t * 2;
                float v0 = acc[mm][nn][half_ * 2];
                float v1 = acc[mm][nn][half_ * 2 + 1];
#pragma unroll
                for (int e = 0; e < 2; e++) {
                    int gnn = gn + e;
                    if (gnn >= N) continue;
                    float v = e ? v1 : v0;
                    if (bias) v += bias[gnn];
                    if (ACT == 1) v = v / (1.f + fabsf(v));
                    if (OSPLIT) {
                        __half hi, lo;
                        split3(v, hi, lo);
                        long base = (long)gr * ldc + 3L * gnn;
                        Cb[base] = hi; Cb[base + 1] = lo; Cb[base + 2] = hi;
                    } else {
                        long ci = (long)gr * ldc + gnn;
                        if (ACCUM) v += Cf[ci];
                        Cf[ci] = v;
                    }
                }
            }
        }
    }
}

// ---- fp32 -> 3-split fp16 conversions (2D grid, no div) ---------------------
// weights: [hi,hi,lo]
__global__ void cvt_w3(const float* __restrict__ W, __half* __restrict__ dst,
                       int K, int ldw, int K3P, int kh, long swh) {
    int n = blockIdx.y;
    int k = blockIdx.x * blockDim.x + threadIdx.x;
    int Kt = (K3P + 2) / 3;
    if (k >= Kt) return;
    float v = 0.f;
    if (k < K) {
        const float* Wp = W;
        int kk = k;
        if (kh && kk >= kh) { Wp += swh; kk -= kh; }
        v = Wp[(long)n * ldw + kk];
    }
    __half hi, lo;
    split3(v, hi, lo);
    long base = (long)n * K3P + 3L * k;
    dst[base] = hi;
    if (3L * k + 1 < K3P) dst[base + 1] = hi;
    if (3L * k + 2 < K3P) dst[base + 2] = lo;
}
// activations: [hi,lo,hi]  (used for w1's windowed input only)
__global__ void cvt_a3(const float* __restrict__ A, __half* __restrict__ dst,
                       int K, int lda, int K3P, long szA, long szD) {
    int z = blockIdx.z;
    A += (long)z * szA; dst += (long)z * szD;
    int r = blockIdx.y;
    int k = blockIdx.x * blockDim.x + threadIdx.x;
    int Kt = (K3P + 2) / 3;
    if (k >= Kt) return;
    float v = (k < K) ? A[(long)r * lda + k] : 0.f;
    __half hi, lo;
    split3(v, hi, lo);
    long base = (long)r * K3P + 3L * k;
    dst[base] = hi;
    if (3L * k + 1 < K3P) dst[base + 1] = lo;
    if (3L * k + 2 < K3P) dst[base + 2] = hi;
}

// ==================== f32x2 SIMT GEMM (day + classifier, exact fp32) ========
__device__ __forceinline__ unsigned long long pack_dup(float a) {
    unsigned long long r;
    unsigned int au = __float_as_uint(a);
    asm("mov.b64 %0, {%1, %1};" : "=l"(r) : "r"(au));
    return r;
}
__device__ __forceinline__ void fma_x2(unsigned long long& acc,
                                       unsigned long long a, unsigned long long b) {
    asm("fma.rn.f32x2 %0, %1, %2, %0;" : "+l"(acc) : "l"(a), "l"(b));
}
__device__ __forceinline__ void unpack_x2(unsigned long long v, float& lo, float& hi) {
    unsigned int ul, uh;
    asm("mov.b64 {%0, %1}, %2;" : "=r"(ul), "=r"(uh) : "l"(v));
    lo = __uint_as_float(ul); hi = __uint_as_float(uh);
}

template<int BM, int BN, int TM, int TN, int TB, int ACT>
__global__ __launch_bounds__((BM/TM)*(BN/TN))
void sgemm(const float* __restrict__ A, const float* __restrict__ W,
           const float* __restrict__ bias, float* __restrict__ C,
           int M, int N, int K, int lda, int ldw, int ldc,
           long sA, long sC, long sW, long sB,
           const int* __restrict__ widx)
{
    constexpr int NT = (BM/TM)*(BN/TN);
    constexpr int LA = BM*8/NT;
    constexpr int LB = BN*8/NT;
    constexpr int NX = BN/TN;

    int bz = blockIdx.z;
    A += (long)bz * sA;
    C += (long)bz * sC;
    {
        int wi = widx ? widx[bz] : bz;
        W += (long)wi * sW;
        if (bias) bias += (long)wi * sB;
    }

    __shared__ __align__(16) float As[8][BM];
    __shared__ __align__(16) float Bs[8][BN];

    int tid = threadIdx.x;
    int tx = tid % NX, ty = tid / NX;
    int row0 = blockIdx.y * BM, col0 = blockIdx.x * BN;

    unsigned long long acc[TM][TN/2];
#pragma unroll
    for (int i = 0; i < TM; i++)
#pragma unroll
        for (int j = 0; j < TN/2; j++) acc[i][j] = 0ull;

    float ra[LA], rb[LB];
    auto loadG = [&](int k0) {
#pragma unroll
        for (int l = 0; l < LA; l++) {
            int i = tid + l * NT;
            int r = i >> 3, c = i & 7;
            int gr = row0 + r, gk = k0 + c;
            ra[l] = (gr < M && gk < K) ? A[(long)gr * lda + gk] : 0.f;
        }
#pragma unroll
        for (int l = 0; l < LB; l++) {
            int i = tid + l * NT;
            int r, c;
            if (TB) { r = i >> 3; c = i & 7; }
            else    { r = i & (BN - 1); c = i / BN; }
            int gn = col0 + r, gk = k0 + c;
            float v = 0.f;
            if (gn < N && gk < K)
                v = TB ? W[(long)gn * ldw + gk] : W[(long)gk * ldw + gn];
            rb[l] = v;
        }
    };
    auto storeS = [&]() {
#pragma unroll
        for (int l = 0; l < LA; l++) {
            int i = tid + l * NT;
            As[i & 7][i >> 3] = ra[l];
        }
#pragma unroll
        for (int l = 0; l < LB; l++) {
            int i = tid + l * NT;
            if (TB) Bs[i & 7][i >> 3] = rb[l];
            else    Bs[i / BN][i & (BN - 1)] = rb[l];
        }
    };
    auto compute = [&]() {
#pragma unroll
        for (int kk = 0; kk < 8; kk++) {
            float a[TM];
            const float4* ap4 = reinterpret_cast<const float4*>(&As[kk][ty * TM]);
#pragma unroll
            for (int q = 0; q < TM/4; q++) {
                float4 tt = ap4[q];
                a[4*q+0] = tt.x; a[4*q+1] = tt.y; a[4*q+2] = tt.z; a[4*q+3] = tt.w;
            }
            unsigned long long bp[TN/2];
            const ulonglong2* bp2 = reinterpret_cast<const ulonglong2*>(&Bs[kk][tx * TN]);
#pragma unroll
            for (int q = 0; q < TN/4; q++) {
                ulonglong2 tt = bp2[q];
                bp[2*q] = tt.x; bp[2*q+1] = tt.y;
            }
#pragma unroll
            for (int i = 0; i < TM; i++) {
                unsigned long long ap = pack_dup(a[i]);
#pragma unroll
                for (int j = 0; j < TN/2; j++) fma_x2(acc[i][j], ap, bp[j]);
            }
        }
    };

    loadG(0);
    storeS();
    __syncthreads();
    for (int k0 = 8; k0 < K; k0 += 8) {
        loadG(k0);
        compute();
        __syncthreads();
        storeS();
        __syncthreads();
    }
    compute();

#pragma unroll
    for (int i = 0; i < TM; i++) {
        int gr = row0 + ty * TM + i;
        if (gr >= M) continue;
#pragma unroll
        for (int j = 0; j < TN/2; j++) {
            float v0, v1;
            unpack_x2(acc[i][j], v0, v1);
            int gn0 = col0 + tx * TN + 2*j;
#pragma unroll
            for (int e = 0; e < 2; e++) {
                int gn = gn0 + e;
                if (gn >= N) continue;
                float v = e ? v1 : v0;
                if (bias) v += bias[gn];
                if (ACT == 1) v = v / (1.f + fabsf(v));
                C[(long)gr * ldc + gn] = v;
            }
        }
    }
}

// -------------------- pointwise kernels -------------------------------------
__global__ void copy_xt(const float* __restrict__ x) {
    int i = blockIdx.x * blockDim.x + threadIdx.x;
    if (i < BB * TT) g_h0[(long)i * DIN + (DIN - 1)] = x[(long)i * DIN + (DIN - 1)];
}

// layernorm fused with fp16 [hi,lo,hi] split -> g_a3 (in_proj input)
__global__ void ln_kernel(const float* __restrict__ w, const float* __restrict__ b) {
    int row = blockIdx.x;
    const float* xr = g_h + (long)row * DM;
    __half* orow = g_a3 + (long)row * K3P_IN;
    int tid = threadIdx.x;
    float v[4], s = 0.f, s2 = 0.f;
#pragma unroll
    for (int i = 0; i < 4; i++) { v[i] = xr[tid + i * 128]; s += v[i]; s2 += v[i] * v[i]; }
#pragma unroll
    for (int o = 16; o > 0; o >>= 1) {
        s  += __shfl_down_sync(0xffffffffu, s, o);
        s2 += __shfl_down_sync(0xffffffffu, s2, o);
    }
    __shared__ float sh[8];
    int wid = tid >> 5, lane = tid & 31;
    if (!lane) { sh[wid] = s; sh[4 + wid] = s2; }
    __syncthreads();
    if (tid == 0) {
        float ts = 0.f, t2 = 0.f;
        for (int i = 0; i < 4; i++) { ts += sh[i]; t2 += sh[4 + i]; }
        sh[0] = ts; sh[4] = t2;
    }
    __syncthreads();
    float mu = sh[0] / (float)DM;
    float var = sh[4] / (float)DM - mu * mu;
    float inv = rsqrtf(var + EPSF);
#pragma unroll
    for (int i = 0; i < 4; i++) {
        int c = tid + i * 128;
        float o = (v[i] - mu) * inv * w[c] + b[c];
        __half hi, lo;
        split3(o, hi, lo);
        orow[3*c] = hi; orow[3*c+1] = lo; orow[3*c+2] = hi;
    }
}

__global__ void conv_kernel(const float* __restrict__ conv_w,
                            const float* __restrict__ conv_b, int layer) {
    long idx = (long)blockIdx.x * blockDim.x + threadIdx.x;
    if (idx >= 2L * M2 * CONVD_) return;
    int c = (int)(idx % CONVD_);
    long r = idx / CONVD_;
    int dir = (int)(r / M2);
    int bt = (int)(r % M2);
    int b = bt / TO, t = bt % TO;
    int m = 2 * layer + dir;
    const float* wc = conv_w + ((long)m * CONVD_ + c) * DCONV;
    const float* zbase = g_zx + (long)dir * M2 * DINP + (long)b * TO * DINP;
    float s = conv_b[(long)m * CONVD_ + c];
#pragma unroll
    for (int j = 0; j < DCONV; j++) {
        int tt = dir ? (t + 3 - j) : (t - 3 + j);
        if (tt >= 0 && tt < TO) s += wc[j] * zbase[(long)tt * DINP + DI_ + c];
    }
    s = s / (1.f + expf(-s));
    g_xbc[(long)dir * M2 * CONVD_ + (long)bt * CONVD_ + c] = s;
}

__device__ __forceinline__ float softplusf(float x) {
    return x > 0.f ? x + log1pf(expf(-x)) : log1pf(expf(x));
}

// scan: grid (HH, BB, 2), 64 threads; 4x16 sub-sum tree for y.
__global__ __launch_bounds__(64)
void scan_kernel(const float* __restrict__ Dp, const float* __restrict__ dtb,
                 const float* __restrict__ alog, int layer) {
    int h = blockIdx.x, b = blockIdx.y, dir = blockIdx.z;
    int m = 2 * layer + dir;
    int p = threadIdx.x;
    float Dh = Dp[m * HH + h];
    float dtbias = dtb[m * HH + h];
    float Aneg = -expf(alog[m * HH + h]);

    __shared__ __align__(16) float sB[2][64], sC[2][64];

    float st[64];
#pragma unroll
    for (int i = 0; i < 64; i++) st[i] = 0.f;

    const float* xbase = g_xbc + (long)dir * M2 * CONVD_ + (long)b * TO * CONVD_;
    float*       ybase = g_y   + (long)dir * M2 * DI_    + (long)b * TO * DI_;
    const float* zbase = g_zx  + ((long)dir * M2 + (long)b * TO) * DINP + DI_ + CONVD_ + h;

    int t0 = dir ? (TO - 1) : 0;
    const float* xr = xbase + (long)t0 * CONVD_;
    float rx = xr[h * 64 + p];
    float rB = xr[DI_ + p];
    float rC = xr[DI_ + DSTATE + p];
    float rraw = zbase[(long)t0 * DINP];

    for (int s_ = 0; s_ < TO; s_++) {
        int buf = s_ & 1;
        int t = dir ? (TO - 1 - s_) : s_;
        sB[buf][p] = rB;
        sC[buf][p] = rC;
        float xcur = rx, rawcur = rraw;
        __syncthreads();
        if (s_ + 1 < TO) {
            int t2 = dir ? (TO - 2 - s_) : (s_ + 1);
            const float* x2 = xbase + (long)t2 * CONVD_;
            rx = x2[h * 64 + p];
            rB = x2[DI_ + p];
            rC = x2[DI_ + DSTATE + p];
            rraw = zbase[(long)t2 * DINP];
        }
        float dt = softplusf(rawcur + dtbias);
        float da = expf(dt * Aneg);
        float dtx = dt * xcur;
        const float4* B4 = reinterpret_cast<const float4*>(sB[buf]);
        const float4* C4 = reinterpret_cast<const float4*>(sC[buf]);
        float ys[4];
#pragma unroll
        for (int gq = 0; gq < 4; gq++) {
            float acc = 0.f;
#pragma unroll
            for (int q = 0; q < 4; q++) {
                int base = gq * 16 + q * 4;
                float4 bn = B4[gq * 4 + q], cn = C4[gq * 4 + q];
                st[base+0] = st[base+0] * da + dtx * bn.x;  acc += st[base+0] * cn.x;
                st[base+1] = st[base+1] * da + dtx * bn.y;  acc += st[base+1] * cn.y;
                st[base+2] = st[base+2] * da + dtx * bn.z;  acc += st[base+2] * cn.z;
                st[base+3] = st[base+3] * da + dtx * bn.w;  acc += st[base+3] * cn.w;
            }
            ys[gq] = acc;
        }
        float y = ys[0] + ys[1] + ys[2] + ys[3] + Dh * xcur;
        ybase[(long)t * DI_ + h * 64 + p] = y;
    }
}

// gated rmsnorm fused with split -> g_a3 row layout [row][ (dir*1024+c)*3 ]
__global__ void gnorm_kernel(const float* __restrict__ norm_w, int layer) {
    int row = blockIdx.x, dir = blockIdx.y;
    int m = 2 * layer + dir;
    const float* yrow = g_y + ((long)dir * M2 + row) * DI_;
    const float* zrow = g_zx + ((long)dir * M2 + row) * DINP;
    __half* orow = g_a3 + (long)row * K3P_OUT + (long)dir * (3 * DI_);
    int tid = threadIdx.x;
    float v[4], ss = 0.f;
#pragma unroll
    for (int i = 0; i < 4; i++) {
        int c = tid + i * 256;
        float z = zrow[c];
        float val = yrow[c] * (z / (1.f + expf(-z)));
        v[i] = val;
        ss += val * val;
    }
#pragma unroll
    for (int o = 16; o > 0; o >>= 1) ss += __shfl_down_sync(0xffffffffu, ss, o);
    __shared__ float sh[8];
    int wid = tid >> 5, lane = tid & 31;
    if (!lane) sh[wid] = ss;
    __syncthreads();
    if (tid == 0) { float tot = 0.f; for (int i = 0; i < 8; i++) tot += sh[i]; sh[0] = tot; }
    __syncthreads();
    float inv = rsqrtf(sh[0] / (float)DI_ + EPSF);
#pragma unroll
    for (int i = 0; i < 4; i++) {
        int c = tid + i * 256;
        float o = v[i] * inv * norm_w[(long)m * DI_ + c];
        __half hi, lo;
        split3(o, hi, lo);
        orow[3*c] = hi; orow[3*c+1] = lo; orow[3*c+2] = hi;
    }
}

// -------------------- host orchestration ------------------------------------
#define SMEM128 (STAGES * (128 + 128) * SPITCH * 2)   /* 61440 */
#define SMEM64  (STAGES * (128 + 64)  * SPITCH * 2)   /* 46080 */

extern "C" void kernel_launch(void* const* d_in, const int* in_sizes, int n_in,
                              void* d_out, int out_size) {
    const float* x        = (const float*)d_in[0];
    const int*   day_idx  = (const int*)  d_in[1];
    const float* day_w    = (const float*)d_in[2];
    const float* day_b    = (const float*)d_in[3];
    const float* w1       = (const float*)d_in[4];
    const float* b1       = (const float*)d_in[5];
    const float* w2       = (const float*)d_in[6];
    const float* b2       = (const float*)d_in[7];
    const float* ln_w     = (const float*)d_in[8];
    const float* ln_b     = (const float*)d_in[9];
    const float* m_in_w   = (const float*)d_in[10];
    const float* m_conv_w = (const float*)d_in[11];
    const float* m_conv_b = (const float*)d_in[12];
    const float* m_dt     = (const float*)d_in[13];
    const float* m_Alog   = (const float*)d_in[14];
    const float* m_D      = (const float*)d_in[15];
    const float* m_norm_w = (const float*)d_in[16];
    const float* m_out_w  = (const float*)d_in[17];
    const float* out_w    = (const float*)d_in[18];
    const float* out_b    = (const float*)d_in[19];
    float* out = (float*)d_out;

    float *h0, *h, *zx;
    __half *a3, *w3, *s3;
    cudaGetSymbolAddress((void**)&h0, g_h0);
    cudaGetSymbolAddress((void**)&h,  g_h);
    cudaGetSymbolAddress((void**)&zx, g_zx);
    cudaGetSymbolAddress((void**)&a3, g_a3);
    cudaGetSymbolAddress((void**)&w3, g_w3);
    cudaGetSymbolAddress((void**)&s3, g_s3);

    cudaFuncSetAttribute(mma_gemm<128,1,0,1>, cudaFuncAttributeMaxDynamicSharedMemorySize, SMEM128);
    cudaFuncSetAttribute(mma_gemm<128,0,0,0>, cudaFuncAttributeMaxDynamicSharedMemorySize, SMEM128);
    cudaFuncSetAttribute(mma_gemm<64,0,0,0>,  cudaFuncAttributeMaxDynamicSharedMemorySize, SMEM64);
    cudaFuncSetAttribute(mma_gemm<64,0,1,0>,  cudaFuncAttributeMaxDynamicSharedMemorySize, SMEM64);

    // 1. day transform (EXACT fp32; per-batch weight) -> g_h0
    sgemm<128,128,8,8, 0,1><<<dim3(4, 16, BB), 256>>>(
        x, day_w, day_b, h0,
        TT, 512, 512, DIN, 512, DIN,
        (long)TT * DIN, (long)TT * DIN, 512L * 512L, 512L, day_idx);

    // 2. passthrough last channel
    copy_xt<<<(BB * TT + 255) / 256, 256>>>(x);

    // 3. w1 patch projection; epilogue writes split fp16 into g_s3 (w2 input)
    cvt_w3<<<dim3(29, PROJD, 1), 256>>>(w1, w3, 7182, 7182, K3P_W1, 0, 0);
    cvt_a3<<<dim3(29, TO, BB), 256>>>(h0, a3, 7182, 4 * DIN, K3P_W1,
                                      (long)TT * DIN, (long)TO * K3P_W1);
    mma_gemm<128,1,0,1><<<dim3(PROJD / 128, 4, BB), 256, SMEM128>>>(
        a3, w3, b1, (void*)s3, TO, PROJD, K3P_W1, K3P_W2,
        (long)TO * K3P_W1, 0, (long)TO * K3P_W2);

    // 4. w2: reads split fp16 from g_s3, writes fp32 h
    cvt_w3<<<dim3(16, DM, 1), 256>>>(w2, w3, PROJD, PROJD, K3P_W2, 0, 0);
    mma_gemm<64,0,0,0><<<dim3(DM / 64, 16, 1), 256, SMEM64>>>(
        s3, w3, b2, (void*)h, M2, DM, K3P_W2, DM, 0, 0, 0);

    // 5. layers
    for (int i = 0; i < LL; i++) {
        // ln fused with split -> a3 (in_proj input, K3P_IN per row)
        ln_kernel<<<M2, 128>>>(ln_w + (long)i * DM, ln_b + (long)i * DM);

        cvt_w3<<<dim3(2, 2 * DINP, 1), 256>>>(
            m_in_w + (long)(2 * i) * DINP * DM, w3, DM, DM, K3P_IN, 0, 0);
        mma_gemm<128,0,0,0><<<dim3((DINP + 127) / 128, 16, 2), 256, SMEM128>>>(
            a3, w3, nullptr, (void*)zx, M2, DINP, K3P_IN, DINP,
            0, (long)DINP * K3P_IN, (long)M2 * DINP);

        conv_kernel<<<(int)((2L * M2 * CONVD_ + 255) / 256), 256>>>(m_conv_w, m_conv_b, i);
        scan_kernel<<<dim3(HH, BB, 2), 64>>>(m_D, m_dt, m_Alog, i);
        // gnorm fused with split -> a3 (out_proj input, K3P_OUT per row)
        gnorm_kernel<<<dim3(M2, 2), 256>>>(m_norm_w, i);

        cvt_w3<<<dim3(8, DM, 1), 256>>>(
            m_out_w + (long)(2 * i) * DM * DI_, w3, 2 * DI_, DI_, K3P_OUT,
            DI_, (long)DM * DI_);
        mma_gemm<64,0,1,0><<<dim3(DM / 64, 16, 1), 256, SMEM64>>>(
            a3, w3, nullptr, (void*)h, M2, DM, K3P_OUT, DM, 0, 0, 0);
    }

    // 6. classifier (small; f32x2 SIMT)
    sgemm<64,64,4,4, 1,0><<<dim3(1, (M2 + 63) / 64, 1), 256>>>(
        h, out_w, out_b, out, M2, 41, DM, DM, DM, 41,
        0, 0, 0, 0, nullptr);
}

// round 14
// speedup vs baseline: 1.0529x; 1.0529x over previous
#include <cuda_runtime.h>
#include <cuda_fp16.h>
#include <math.h>
#include <stdint.h>

#define BB 4
#define TT 2048
#define DIN 513
#define TO 509
#define M2 (BB*TO)       /* 2036 */
#define DM 512
#define PROJD 4096
#define LL 5
#define DSTATE 64
#define DCONV 4
#define DI_ 1024
#define HH 16
#define CONVD_ 1152      /* DI + 2*DSTATE */
#define DINP 2192        /* 2*DI + 2*DSTATE + H */
#define EPSF 1e-5f

#define K3P_IN  1536     /* 3*512  */
#define K3P_W2  12288    /* 3*4096 */
#define K3P_OUT 6144     /* 3*2048 */
#define K3P_W1  21568    /* 3*7182=21546 padded to 32-mult */

// -------------------- scratch (device globals; no runtime alloc) ------------
__device__ float g_h0[(size_t)BB*TT*DIN];
__device__ float g_h [(size_t)M2*DM];
__device__ float g_zx[(size_t)2*M2*DINP];
__device__ float g_xbc[(size_t)2*M2*CONVD_];
__device__ float g_y [(size_t)2*M2*DI_];
__device__ __align__(16) __half g_a3[(size_t)BB*TO*K3P_W1];   // 43.9M
__device__ __align__(16) __half g_w3[(size_t)PROJD*K3P_W1];   // 88.3M
__device__ __align__(16) __half g_s3[(size_t)M2*K3P_W2];      // 25.0M
__device__ __align__(16) __half g_wm[(size_t)10*DINP*K3P_IN + (size_t)LL*DM*K3P_OUT]; // 49.4M

__device__ __forceinline__ uint32_t smem_u32(const void* p) {
    uint32_t a;
    asm("{ .reg .u64 t; cvta.to.shared.u64 t, %1; cvt.u32.u64 %0, t; }"
        : "=r"(a) : "l"(p));
    return a;
}

// fp16 2-term split: hi+lo captures ~24 mantissa bits (fp32-class)
__device__ __forceinline__ void split3(float v, __half& hi, __half& lo) {
    hi = __float2half_rn(v);
    lo = __float2half_rn(v - __half2float(hi));
}

// ==================== mma.sync fp16 GEMM, 3-stage cp.async pipeline =========
// C = A3[M,K3] @ W3[N,K3]^T  (K3 % 32 == 0). 256 threads.
// OSPLIT=1: output written as fp16 [hi,lo,hi] triples (ldc = split elems/row).
#define SPITCH 40   /* halfs per smem row (32 data + 8 pad) = 80 bytes */
#define STAGES 3

template<int BN, int ACT, int ACCUM, int OSPLIT>
__global__ __launch_bounds__(256)
void mma_gemm(const __half* __restrict__ A, const __half* __restrict__ W,
              const float* __restrict__ bias, void* __restrict__ Cv,
              int M, int N, int K3, int ldc, long sA, long sW, long sC,
              const int* __restrict__ bidx, long sBias)
{
    constexpr int NN = BN / 16;
    constexpr int NB = BN / 32;
    constexpr int LB = BN / 64;
    constexpr int ABYTES = 128 * SPITCH * 2;
    constexpr int BBYTES = BN  * SPITCH * 2;

    extern __shared__ __align__(16) char dsm[];
    uint32_t asb = smem_u32(dsm);
    uint32_t bsb = asb + STAGES * ABYTES;

    int tid = threadIdx.x;
    int wid = tid >> 5, lane = tid & 31;
    int z = blockIdx.z;
    A += (long)z * sA;  W += (long)z * sW;
    if (bias && bidx) bias += (long)bidx[z] * sBias;
    int row0 = blockIdx.y * 128, col0 = blockIdx.x * BN;
    int wm = wid & 3, wn = wid >> 2;

    float acc[2][NN][4];
#pragma unroll
    for (int i = 0; i < 2; i++)
#pragma unroll
        for (int j = 0; j < NN; j++)
#pragma unroll
            for (int q = 0; q < 4; q++) acc[i][j][q] = 0.f;

    auto loadStage = [&](int ch, int s) {
        int k0 = ch << 5;
        uint32_t sa = asb + s * ABYTES;
#pragma unroll
        for (int l = 0; l < 2; l++) {
            int idx = tid + l * 256;
            int r = idx >> 2, c = idx & 3;
            int gr = row0 + r;
            int grc = gr < M ? gr : M - 1;
            const __half* src = A + (long)grc * K3 + k0 + c * 8;
            uint32_t dst = sa + (uint32_t)(r * (SPITCH * 2) + c * 16);
            int bytes = (gr < M) ? 16 : 0;
            asm volatile("cp.async.cg.shared.global [%0], [%1], 16, %2;"
                :: "r"(dst), "l"(src), "r"(bytes));
        }
        uint32_t sb2 = bsb + s * BBYTES;
#pragma unroll
        for (int l = 0; l < LB; l++) {
            int idx = tid + l * 256;
            int r = idx >> 2, c = idx & 3;
            int gn = col0 + r;
            int gnc = gn < N ? gn : N - 1;
            const __half* src = W + (long)gnc * K3 + k0 + c * 8;
            uint32_t dst = sb2 + (uint32_t)(r * (SPITCH * 2) + c * 16);
            int bytes = (gn < N) ? 16 : 0;
            asm volatile("cp.async.cg.shared.global [%0], [%1], 16, %2;"
                :: "r"(dst), "l"(src), "r"(bytes));
        }
        asm volatile("cp.async.commit_group;" ::: "memory");
    };

    auto compute = [&](int s) {
        uint32_t a_base = asb + s * ABYTES
            + (uint32_t)((wm * 32 + (lane & 15)) * 80 + (lane >> 4) * 16);
        uint32_t b_base = bsb + s * BBYTES
            + (uint32_t)((wn * (BN / 2) + ((lane >> 4) & 1) * 8 + (lane & 7)) * 80
                         + ((lane >> 3) & 1) * 16);
#pragma unroll
        for (int ks = 0; ks < 2; ks++) {
            uint32_t a[2][4];
#pragma unroll
            for (int mm = 0; mm < 2; mm++) {
                uint32_t ad = a_base + (uint32_t)(mm * 16 * 80 + ks * 32);
                asm volatile("ldmatrix.sync.aligned.m8n8.x4.shared.b16 {%0,%1,%2,%3}, [%4];"
                    : "=r"(a[mm][0]), "=r"(a[mm][1]), "=r"(a[mm][2]), "=r"(a[mm][3])
                    : "r"(ad));
            }
            uint32_t b[NB][4];
#pragma unroll
            for (int nb = 0; nb < NB; nb++) {
                uint32_t bd = b_base + (uint32_t)(nb * 16 * 80 + ks * 32);
                asm volatile("ldmatrix.sync.aligned.m8n8.x4.shared.b16 {%0,%1,%2,%3}, [%4];"
                    : "=r"(b[nb][0]), "=r"(b[nb][1]), "=r"(b[nb][2]), "=r"(b[nb][3])
                    : "r"(bd));
            }
#pragma unroll
            for (int mm = 0; mm < 2; mm++)
#pragma unroll
                for (int nn = 0; nn < NN; nn++) {
                    uint32_t b0 = b[nn >> 1][(nn & 1) * 2];
                    uint32_t b1 = b[nn >> 1][(nn & 1) * 2 + 1];
                    asm volatile(
                        "mma.sync.aligned.m16n8k16.row.col.f32.f16.f16.f32 "
                        "{%0,%1,%2,%3}, {%4,%5,%6,%7}, {%8,%9}, {%0,%1,%2,%3};"
                        : "+f"(acc[mm][nn][0]), "+f"(acc[mm][nn][1]),
                          "+f"(acc[mm][nn][2]), "+f"(acc[mm][nn][3])
                        : "r"(a[mm][0]), "r"(a[mm][1]), "r"(a[mm][2]), "r"(a[mm][3]),
                          "r"(b0), "r"(b1));
                }
        }
    };

    int NC = K3 >> 5;
    loadStage(0, 0);
    loadStage(1, 1);
    for (int ch = 0; ch < NC; ch++) {
        // Final chunk has only ONE pending group -> must drain fully (race fix).
        if (ch + 1 < NC)
            asm volatile("cp.async.wait_group 1;" ::: "memory");
        else
            asm volatile("cp.async.wait_group 0;" ::: "memory");
        __syncthreads();
        // Issue next-next stage BEFORE compute: slot (ch+2)%3 was last read by
        // compute(ch-1), fenced by the barrier above. Loads overlap compute.
        int nx = ch + 2;
        if (nx < NC) loadStage(nx, nx % 3);
        compute(ch % 3);
    }

    float* Cf = (float*)Cv + (OSPLIT ? 0 : (long)z * sC);
    __half* Cb = (__half*)Cv + (OSPLIT ? (long)z * sC : 0);

    int g = lane >> 2, t = lane & 3;
#pragma unroll
    for (int mm = 0; mm < 2; mm++) {
#pragma unroll
        for (int half_ = 0; half_ < 2; half_++) {
            int gr = row0 + wm * 32 + mm * 16 + g + half_ * 8;
            if (gr >= M) continue;
#pragma unroll
            for (int nn = 0; nn < NN; nn++) {
                int gn = col0 + wn * (BN / 2) + nn * 8 + t * 2;
                float v0 = acc[mm][nn][half_ * 2];
                float v1 = acc[mm][nn][half_ * 2 + 1];
#pragma unroll
                for (int e = 0; e < 2; e++) {
                    int gnn = gn + e;
                    if (gnn >= N) continue;
                    float v = e ? v1 : v0;
                    if (bias) v += bias[gnn];
                    if (ACT == 1) v = v / (1.f + fabsf(v));
                    if (OSPLIT) {
                        __half hi, lo;
                        split3(v, hi, lo);
                        long base = (long)gr * ldc + 3L * gnn;
                        Cb[base] = hi; Cb[base + 1] = lo; Cb[base + 2] = hi;
                    } else {
                        long ci = (long)gr * ldc + gnn;
                        if (ACCUM) v += Cf[ci];
                        Cf[ci] = v;
                    }
                }
            }
        }
    }
}

// ---- fp32 -> 3-split fp16 conversions (2D grid, no div) ---------------------
// weights: [hi,hi,lo]
__global__ void cvt_w3(const float* __restrict__ W, __half* __restrict__ dst,
                       int K, int ldw, int K3P, int kh, long swh) {
    int n = blockIdx.y;
    int k = blockIdx.x * blockDim.x + threadIdx.x;
    int Kt = (K3P + 2) / 3;
    if (k >= Kt) return;
    float v = 0.f;
    if (k < K) {
        const float* Wp = W;
        int kk = k;
        if (kh && kk >= kh) { Wp += swh; kk -= kh; }
        v = Wp[(long)n * ldw + kk];
    }
    __half hi, lo;
    split3(v, hi, lo);
    long base = (long)n * K3P + 3L * k;
    dst[base] = hi;
    if (3L * k + 1 < K3P) dst[base + 1] = hi;
    if (3L * k + 2 < K3P) dst[base + 2] = lo;
}
// day weights, transposed read + day_idx gather: W3[n][3k] from W[k*512+n]
__global__ void cvt_w3_day(const float* __restrict__ day_w, const int* __restrict__ day_idx,
                           __half* __restrict__ dst) {
    int z = blockIdx.z;
    const float* W = day_w + (long)day_idx[z] * 512 * 512;
    int n = blockIdx.y;
    int k = blockIdx.x * blockDim.x + threadIdx.x;
    if (k >= 512) return;
    float v = W[(long)k * 512 + n];
    __half hi, lo;
    split3(v, hi, lo);
    long base = (long)z * 512 * K3P_IN + (long)n * K3P_IN + 3L * k;
    dst[base] = hi; dst[base + 1] = hi; dst[base + 2] = lo;
}
// activations: [hi,lo,hi]
__global__ void cvt_a3(const float* __restrict__ A, __half* __restrict__ dst,
                       int K, int lda, int K3P, long szA, long szD) {
    int z = blockIdx.z;
    A += (long)z * szA; dst += (long)z * szD;
    int r = blockIdx.y;
    int k = blockIdx.x * blockDim.x + threadIdx.x;
    int Kt = (K3P + 2) / 3;
    if (k >= Kt) return;
    float v = (k < K) ? A[(long)r * lda + k] : 0.f;
    __half hi, lo;
    split3(v, hi, lo);
    long base = (long)r * K3P + 3L * k;
    dst[base] = hi;
    if (3L * k + 1 < K3P) dst[base + 1] = lo;
    if (3L * k + 2 < K3P) dst[base + 2] = hi;
}

// ==================== f32x2 SIMT GEMM (classifier, exact fp32) ==============
__device__ __forceinline__ unsigned long long pack_dup(float a) {
    unsigned long long r;
    unsigned int au = __float_as_uint(a);
    asm("mov.b64 %0, {%1, %1};" : "=l"(r) : "r"(au));
    return r;
}
__device__ __forceinline__ void fma_x2(unsigned long long& acc,
                                       unsigned long long a, unsigned long long b) {
    asm("fma.rn.f32x2 %0, %1, %2, %0;" : "+l"(acc) : "l"(a), "l"(b));
}
__device__ __forceinline__ void unpack_x2(unsigned long long v, float& lo, float& hi) {
    unsigned int ul, uh;
    asm("mov.b64 {%0, %1}, %2;" : "=r"(ul), "=r"(uh) : "l"(v));
    lo = __uint_as_float(ul); hi = __uint_as_float(uh);
}

template<int BM, int BN, int TM, int TN>
__global__ __launch_bounds__((BM/TM)*(BN/TN))
void sgemm(const float* __restrict__ A, const float* __restrict__ W,
           const float* __restrict__ bias, float* __restrict__ C,
           int M, int N, int K, int lda, int ldw, int ldc)
{
    constexpr int NT = (BM/TM)*(BN/TN);
    constexpr int LA = BM*8/NT;
    constexpr int LB = BN*8/NT;
    constexpr int NX = BN/TN;

    __shared__ __align__(16) float As[8][BM];
    __shared__ __align__(16) float Bs[8][BN];

    int tid = threadIdx.x;
    int tx = tid % NX, ty = tid / NX;
    int row0 = blockIdx.y * BM, col0 = blockIdx.x * BN;

    unsigned long long acc[TM][TN/2];
#pragma unroll
    for (int i = 0; i < TM; i++)
#pragma unroll
        for (int j = 0; j < TN/2; j++) acc[i][j] = 0ull;

    float ra[LA], rb[LB];
    auto loadG = [&](int k0) {
#pragma unroll
        for (int l = 0; l < LA; l++) {
            int i = tid + l * NT;
            int r = i >> 3, c = i & 7;
            int gr = row0 + r, gk = k0 + c;
            ra[l] = (gr < M && gk < K) ? A[(long)gr * lda + gk] : 0.f;
        }
#pragma unroll
        for (int l = 0; l < LB; l++) {
            int i = tid + l * NT;
            int r = i >> 3, c = i & 7;
            int gn = col0 + r, gk = k0 + c;
            rb[l] = (gn < N && gk < K) ? W[(long)gn * ldw + gk] : 0.f;
        }
    };
    auto storeS = [&]() {
#pragma unroll
        for (int l = 0; l < LA; l++) {
            int i = tid + l * NT;
            As[i & 7][i >> 3] = ra[l];
        }
#pragma unroll
        for (int l = 0; l < LB; l++) {
            int i = tid + l * NT;
            Bs[i & 7][i >> 3] = rb[l];
        }
    };
    auto compute = [&]() {
#pragma unroll
        for (int kk = 0; kk < 8; kk++) {
            float a[TM];
            const float4* ap4 = reinterpret_cast<const float4*>(&As[kk][ty * TM]);
#pragma unroll
            for (int q = 0; q < TM/4; q++) {
                float4 tt = ap4[q];
                a[4*q+0] = tt.x; a[4*q+1] = tt.y; a[4*q+2] = tt.z; a[4*q+3] = tt.w;
            }
            unsigned long long bp[TN/2];
            const ulonglong2* bp2 = reinterpret_cast<const ulonglong2*>(&Bs[kk][tx * TN]);
#pragma unroll
            for (int q = 0; q < TN/4; q++) {
                ulonglong2 tt = bp2[q];
                bp[2*q] = tt.x; bp[2*q+1] = tt.y;
            }
#pragma unroll
            for (int i = 0; i < TM; i++) {
                unsigned long long ap = pack_dup(a[i]);
#pragma unroll
                for (int j = 0; j < TN/2; j++) fma_x2(acc[i][j], ap, bp[j]);
            }
        }
    };

    loadG(0);
    storeS();
    __syncthreads();
    for (int k0 = 8; k0 < K; k0 += 8) {
        loadG(k0);
        compute();
        __syncthreads();
        storeS();
        __syncthreads();
    }
    compute();

#pragma unroll
    for (int i = 0; i < TM; i++) {
        int gr = row0 + ty * TM + i;
        if (gr >= M) continue;
#pragma unroll
        for (int j = 0; j < TN/2; j++) {
            float v0, v1;
            unpack_x2(acc[i][j], v0, v1);
            int gn0 = col0 + tx * TN + 2*j;
#pragma unroll
            for (int e = 0; e < 2; e++) {
                int gn = gn0 + e;
                if (gn >= N) continue;
                float v = e ? v1 : v0;
                if (bias) v += bias[gn];
                C[(long)gr * ldc + gn] = v;
            }
        }
    }
}

// -------------------- pointwise kernels -------------------------------------
__global__ void copy_xt(const float* __restrict__ x) {
    int i = blockIdx.x * blockDim.x + threadIdx.x;
    if (i < BB * TT) g_h0[(long)i * DIN + (DIN - 1)] = x[(long)i * DIN + (DIN - 1)];
}

// layernorm fused with fp16 [hi,lo,hi] split -> g_a3 (in_proj input)
__global__ void ln_kernel(const float* __restrict__ w, const float* __restrict__ b) {
    int row = blockIdx.x;
    const float* xr = g_h + (long)row * DM;
    __half* orow = g_a3 + (long)row * K3P_IN;
    int tid = threadIdx.x;
    float v[4], s = 0.f, s2 = 0.f;
#pragma unroll
    for (int i = 0; i < 4; i++) { v[i] = xr[tid + i * 128]; s += v[i]; s2 += v[i] * v[i]; }
#pragma unroll
    for (int o = 16; o > 0; o >>= 1) {
        s  += __shfl_down_sync(0xffffffffu, s, o);
        s2 += __shfl_down_sync(0xffffffffu, s2, o);
    }
    __shared__ float sh[8];
    int wid = tid >> 5, lane = tid & 31;
    if (!lane) { sh[wid] = s; sh[4 + wid] = s2; }
    __syncthreads();
    if (tid == 0) {
        float ts = 0.f, t2 = 0.f;
        for (int i = 0; i < 4; i++) { ts += sh[i]; t2 += sh[4 + i]; }
        sh[0] = ts; sh[4] = t2;
    }
    __syncthreads();
    float mu = sh[0] / (float)DM;
    float var = sh[4] / (float)DM - mu * mu;
    float inv = rsqrtf(var + EPSF);
#pragma unroll
    for (int i = 0; i < 4; i++) {
        int c = tid + i * 128;
        float o = (v[i] - mu) * inv * w[c] + b[c];
        __half hi, lo;
        split3(o, hi, lo);
        orow[3*c] = hi; orow[3*c+1] = lo; orow[3*c+2] = hi;
    }
}

__global__ void conv_kernel(const float* __restrict__ conv_w,
                            const float* __restrict__ conv_b, int layer) {
    long idx = (long)blockIdx.x * blockDim.x + threadIdx.x;
    if (idx >= 2L * M2 * CONVD_) return;
    int c = (int)(idx % CONVD_);
    long r = idx / CONVD_;
    int dir = (int)(r / M2);
    int bt = (int)(r % M2);
    int b = bt / TO, t = bt % TO;
    int m = 2 * layer + dir;
    const float* wc = conv_w + ((long)m * CONVD_ + c) * DCONV;
    const float* zbase = g_zx + (long)dir * M2 * DINP + (long)b * TO * DINP;
    float s = conv_b[(long)m * CONVD_ + c];
#pragma unroll
    for (int j = 0; j < DCONV; j++) {
        int tt = dir ? (t + 3 - j) : (t - 3 + j);
        if (tt >= 0 && tt < TO) s += wc[j] * zbase[(long)tt * DINP + DI_ + c];
    }
    s = s / (1.f + expf(-s));
    g_xbc[(long)dir * M2 * CONVD_ + (long)bt * CONVD_ + c] = s;
}

__device__ __forceinline__ float softplusf(float x) {
    return x > 0.f ? x + log1pf(expf(-x)) : log1pf(expf(x));
}

// scan: grid (HH, BB, 2), 64 threads; 4x16 sub-sum tree for y.
__global__ __launch_bounds__(64)
void scan_kernel(const float* __restrict__ Dp, const float* __restrict__ dtb,
                 const float* __restrict__ alog, int layer) {
    int h = blockIdx.x, b = blockIdx.y, dir = blockIdx.z;
    int m = 2 * layer + dir;
    int p = threadIdx.x;
    float Dh = Dp[m * HH + h];
    float dtbias = dtb[m * HH + h];
    float Aneg = -expf(alog[m * HH + h]);

    __shared__ __align__(16) float sB[2][64], sC[2][64];

    float st[64];
#pragma unroll
    for (int i = 0; i < 64; i++) st[i] = 0.f;

    const float* xbase = g_xbc + (long)dir * M2 * CONVD_ + (long)b * TO * CONVD_;
    float*       ybase = g_y   + (long)dir * M2 * DI_    + (long)b * TO * DI_;
    const float* zbase = g_zx  + ((long)dir * M2 + (long)b * TO) * DINP + DI_ + CONVD_ + h;

    int t0 = dir ? (TO - 1) : 0;
    const float* xr = xbase + (long)t0 * CONVD_;
    float rx = xr[h * 64 + p];
    float rB = xr[DI_ + p];
    float rC = xr[DI_ + DSTATE + p];
    float rraw = zbase[(long)t0 * DINP];

    for (int s_ = 0; s_ < TO; s_++) {
        int buf = s_ & 1;
        int t = dir ? (TO - 1 - s_) : s_;
        sB[buf][p] = rB;
        sC[buf][p] = rC;
        float xcur = rx, rawcur = rraw;
        __syncthreads();
        if (s_ + 1 < TO) {
            int t2 = dir ? (TO - 2 - s_) : (s_ + 1);
            const float* x2 = xbase + (long)t2 * CONVD_;
            rx = x2[h * 64 + p];
            rB = x2[DI_ + p];
            rC = x2[DI_ + DSTATE + p];
            rraw = zbase[(long)t2 * DINP];
        }
        float dt = softplusf(rawcur + dtbias);
        float da = expf(dt * Aneg);
        float dtx = dt * xcur;
        const float4* B4 = reinterpret_cast<const float4*>(sB[buf]);
        const float4* C4 = reinterpret_cast<const float4*>(sC[buf]);
        float ys[4];
#pragma unroll
        for (int gq = 0; gq < 4; gq++) {
            float acc = 0.f;
#pragma unroll
            for (int q = 0; q < 4; q++) {
                int base = gq * 16 + q * 4;
                float4 bn = B4[gq * 4 + q], cn = C4[gq * 4 + q];
                st[base+0] = st[base+0] * da + dtx * bn.x;  acc += st[base+0] * cn.x;
                st[base+1] = st[base+1] * da + dtx * bn.y;  acc += st[base+1] * cn.y;
                st[base+2] = st[base+2] * da + dtx * bn.z;  acc += st[base+2] * cn.z;
                st[base+3] = st[base+3] * da + dtx * bn.w;  acc += st[base+3] * cn.w;
            }
            ys[gq] = acc;
        }
        float y = ys[0] + ys[1] + ys[2] + ys[3] + Dh * xcur;
        ybase[(long)t * DI_ + h * 64 + p] = y;
    }
}

// gated rmsnorm fused with split -> g_a3 row layout [row][ (dir*1024+c)*3 ]
__global__ void gnorm_kernel(const float* __restrict__ norm_w, int layer) {
    int row = blockIdx.x, dir = blockIdx.y;
    int m = 2 * layer + dir;
    const float* yrow = g_y + ((long)dir * M2 + row) * DI_;
    const float* zrow = g_zx + ((long)dir * M2 + row) * DINP;
    __half* orow = g_a3 + (long)row * K3P_OUT + (long)dir * (3 * DI_);
    int tid = threadIdx.x;
    float v[4], ss = 0.f;
#pragma unroll
    for (int i = 0; i < 4; i++) {
        int c = tid + i * 256;
        float z = zrow[c];
        float val = yrow[c] * (z / (1.f + expf(-z)));
        v[i] = val;
        ss += val * val;
    }
#pragma unroll
    for (int o = 16; o > 0; o >>= 1) ss += __shfl_down_sync(0xffffffffu, ss, o);
    __shared__ float sh[8];
    int wid = tid >> 5, lane = tid & 31;
    if (!lane) sh[wid] = ss;
    __syncthreads();
    if (tid == 0) { float tot = 0.f; for (int i = 0; i < 8; i++) tot += sh[i]; sh[0] = tot; }
    __syncthreads();
    float inv = rsqrtf(sh[0] / (float)DI_ + EPSF);
#pragma unroll
    for (int i = 0; i < 4; i++) {
        int c = tid + i * 256;
        float o = v[i] * inv * norm_w[(long)m * DI_ + c];
        __half hi, lo;
        split3(o, hi, lo);
        orow[3*c] = hi; orow[3*c+1] = lo; orow[3*c+2] = hi;
    }
}

// -------------------- host orchestration ------------------------------------
#define SMEM128 (STAGES * (128 + 128) * SPITCH * 2)   /* 61440 */
#define SMEM64  (STAGES * (128 + 64)  * SPITCH * 2)   /* 46080 */

extern "C" void kernel_launch(void* const* d_in, const int* in_sizes, int n_in,
                              void* d_out, int out_size) {
    const float* x        = (const float*)d_in[0];
    const int*   day_idx  = (const int*)  d_in[1];
    const float* day_w    = (const float*)d_in[2];
    const float* day_b    = (const float*)d_in[3];
    const float* w1       = (const float*)d_in[4];
    const float* b1       = (const float*)d_in[5];
    const float* w2       = (const float*)d_in[6];
    const float* b2       = (const float*)d_in[7];
    const float* ln_w     = (const float*)d_in[8];
    const float* ln_b     = (const float*)d_in[9];
    const float* m_in_w   = (const float*)d_in[10];
    const float* m_conv_w = (const float*)d_in[11];
    const float* m_conv_b = (const float*)d_in[12];
    const float* m_dt     = (const float*)d_in[13];
    const float* m_Alog   = (const float*)d_in[14];
    const float* m_D      = (const float*)d_in[15];
    const float* m_norm_w = (const float*)d_in[16];
    const float* m_out_w  = (const float*)d_in[17];
    const float* out_w    = (const float*)d_in[18];
    const float* out_b    = (const float*)d_in[19];
    float* out = (float*)d_out;

    float *h0, *h, *zx;
    __half *a3, *w3, *s3, *wm;
    cudaGetSymbolAddress((void**)&h0, g_h0);
    cudaGetSymbolAddress((void**)&h,  g_h);
    cudaGetSymbolAddress((void**)&zx, g_zx);
    cudaGetSymbolAddress((void**)&a3, g_a3);
    cudaGetSymbolAddress((void**)&w3, g_w3);
    cudaGetSymbolAddress((void**)&s3, g_s3);
    cudaGetSymbolAddress((void**)&wm, g_wm);
    __half* wm_out = wm + (size_t)10 * DINP * K3P_IN;

    cudaFuncSetAttribute(mma_gemm<128,1,0,0>, cudaFuncAttributeMaxDynamicSharedMemorySize, SMEM128);
    cudaFuncSetAttribute(mma_gemm<128,1,0,1>, cudaFuncAttributeMaxDynamicSharedMemorySize, SMEM128);
    cudaFuncSetAttribute(mma_gemm<128,0,0,0>, cudaFuncAttributeMaxDynamicSharedMemorySize, SMEM128);
    cudaFuncSetAttribute(mma_gemm<64,0,0,0>,  cudaFuncAttributeMaxDynamicSharedMemorySize, SMEM64);
    cudaFuncSetAttribute(mma_gemm<64,0,1,0>,  cudaFuncAttributeMaxDynamicSharedMemorySize, SMEM64);

    // 0. hoisted weight conversions (constant w.r.t. activations)
    //    all 10 in_proj weights: [10*DINP rows, K=DM]
    cvt_w3<<<dim3(2, 10 * DINP, 1), 256>>>(m_in_w, wm, DM, DM, K3P_IN, 0, 0);
    //    5 fused out_proj weights (dirs along K)
    for (int i = 0; i < LL; i++)
        cvt_w3<<<dim3(8, DM, 1), 256>>>(
            m_out_w + (long)(2 * i) * DM * DI_, wm_out + (long)i * DM * K3P_OUT,
            2 * DI_, DI_, K3P_OUT, DI_, (long)DM * DI_);

    // 1. day transform via mma (softsign, per-batch gathered weight+bias)
    cvt_w3_day<<<dim3(2, 512, BB), 256>>>(day_w, day_idx, s3);
    cvt_a3<<<dim3(2, TT, BB), 256>>>(x, a3, 512, DIN, K3P_IN,
                                     (long)TT * DIN, (long)TT * K3P_IN);
    mma_gemm<128,1,0,0><<<dim3(4, 16, BB), 256, SMEM128>>>(
        a3, s3, day_b, (void*)h0, TT, 512, K3P_IN, DIN,
        (long)TT * K3P_IN, 512L * K3P_IN, (long)TT * DIN, day_idx, 512);

    // 2. passthrough last channel
    copy_xt<<<(BB * TT + 255) / 256, 256>>>(x);

    // 3. w1 patch projection; epilogue writes split fp16 into g_s3 (w2 input)
    cvt_w3<<<dim3(29, PROJD, 1), 256>>>(w1, w3, 7182, 7182, K3P_W1, 0, 0);
    cvt_a3<<<dim3(29, TO, BB), 256>>>(h0, a3, 7182, 4 * DIN, K3P_W1,
                                      (long)TT * DIN, (long)TO * K3P_W1);
    mma_gemm<128,1,0,1><<<dim3(PROJD / 128, 4, BB), 256, SMEM128>>>(
        a3, w3, b1, (void*)s3, TO, PROJD, K3P_W1, K3P_W2,
        (long)TO * K3P_W1, 0, (long)TO * K3P_W2, nullptr, 0);

    // 4. w2: reads split fp16 from g_s3, writes fp32 h
    cvt_w3<<<dim3(16, DM, 1), 256>>>(w2, w3, PROJD, PROJD, K3P_W2, 0, 0);
    mma_gemm<64,0,0,0><<<dim3(DM / 64, 16, 1), 256, SMEM64>>>(
        s3, w3, b2, (void*)h, M2, DM, K3P_W2, DM, 0, 0, 0, nullptr, 0);

    // 5. layers
    for (int i = 0; i < LL; i++) {
        // ln fused with split -> a3 (in_proj input, K3P_IN per row)
        ln_kernel<<<M2, 128>>>(ln_w + (long)i * DM, ln_b + (long)i * DM);

        mma_gemm<128,0,0,0><<<dim3((DINP + 127) / 128, 16, 2), 256, SMEM128>>>(
            a3, wm + (long)(2 * i) * DINP * K3P_IN, nullptr, (void*)zx,
            M2, DINP, K3P_IN, DINP,
            0, (long)DINP * K3P_IN, (long)M2 * DINP, nullptr, 0);

        conv_kernel<<<(int)((2L * M2 * CONVD_ + 255) / 256), 256>>>(m_conv_w, m_conv_b, i);
        scan_kernel<<<dim3(HH, BB, 2), 64>>>(m_D, m_dt, m_Alog, i);
        // gnorm fused with split -> a3 (out_proj input, K3P_OUT per row)
        gnorm_kernel<<<dim3(M2, 2), 256>>>(m_norm_w, i);

        mma_gemm<64,0,1,0><<<dim3(DM / 64, 16, 1), 256, SMEM64>>>(
            a3, wm_out + (long)i * DM * K3P_OUT, nullptr, (void*)h,
            M2, DM, K3P_OUT, DM, 0, 0, 0, nullptr, 0);
    }

    // 6. classifier (small; f32x2 SIMT)
    sgemm<64,64,4,4><<<dim3(1, (M2 + 63) / 64, 1), 256>>>(
        h, out_w, out_b, out, M2, 41, DM, DM, DM, 41);
}

// round 15
// speedup vs baseline: 1.0963x; 1.0412x over previous
#include <cuda_runtime.h>
#include <cuda_fp16.h>
#include <math.h>
#include <stdint.h>

#define BB 4
#define TT 2048
#define DIN 513
#define TO 509
#define M2 (BB*TO)       /* 2036 */
#define DM 512
#define PROJD 4096
#define LL 5
#define DSTATE 64
#define DCONV 4
#define DI_ 1024
#define HH 16
#define CONVD_ 1152      /* DI + 2*DSTATE */
#define DINP 2192        /* 2*DI + 2*DSTATE + H */
#define EPSF 1e-5f

#define K3P_IN  1536     /* 3*512  */
#define K3P_W2  12288    /* 3*4096 */
#define K3P_OUT 6144     /* 3*2048 */
#define K3P_W1  21568    /* 3*7182=21546 padded to 32-mult */

// -------------------- scratch (device globals; no runtime alloc) ------------
__device__ float g_h0[(size_t)BB*TT*DIN];
__device__ float g_h [(size_t)M2*DM];
__device__ float g_zx[(size_t)2*M2*DINP];
__device__ float g_xbc[(size_t)2*M2*CONVD_];
__device__ float g_y [(size_t)2*M2*DI_];
__device__ __align__(16) __half g_a3[(size_t)BB*TO*K3P_W1];   // 43.9M
__device__ __align__(16) __half g_w3[(size_t)PROJD*K3P_W1];   // 88.3M
__device__ __align__(16) __half g_s3[(size_t)M2*K3P_W2];      // 25.0M
__device__ __align__(16) __half g_wm[(size_t)10*DINP*K3P_IN + (size_t)LL*DM*K3P_OUT]; // 49.4M

__device__ __forceinline__ uint32_t smem_u32(const void* p) {
    uint32_t a;
    asm("{ .reg .u64 t; cvta.to.shared.u64 t, %1; cvt.u32.u64 %0, t; }"
        : "=r"(a) : "l"(p));
    return a;
}

// fp16 2-term split: hi+lo captures ~24 mantissa bits (fp32-class)
__device__ __forceinline__ void split3(float v, __half& hi, __half& lo) {
    hi = __float2half_rn(v);
    lo = __float2half_rn(v - __half2float(hi));
}

// ==================== mma.sync fp16 GEMM, 3-stage cp.async pipeline =========
// C = A3[M,K3] @ W3[N,K3]^T  (K3 % 32 == 0). 256 threads.
// OSPLIT=1: output written as fp16 [hi,lo,hi] triples (ldc = split elems/row).
#define SPITCH 40   /* halfs per smem row (32 data + 8 pad) = 80 bytes */
#define STAGES 3

template<int BN, int ACT, int ACCUM, int OSPLIT>
__global__ __launch_bounds__(256)
void mma_gemm(const __half* __restrict__ A, const __half* __restrict__ W,
              const float* __restrict__ bias, void* __restrict__ Cv,
              int M, int N, int K3, int ldc, long sA, long sW, long sC,
              const int* __restrict__ bidx, long sBias)
{
    constexpr int NN = BN / 16;
    constexpr int NB = BN / 32;
    constexpr int LB = BN / 64;
    constexpr int ABYTES = 128 * SPITCH * 2;
    constexpr int BBYTES = BN  * SPITCH * 2;

    extern __shared__ __align__(16) char dsm[];
    uint32_t asb = smem_u32(dsm);
    uint32_t bsb = asb + STAGES * ABYTES;

    int tid = threadIdx.x;
    int wid = tid >> 5, lane = tid & 31;
    int z = blockIdx.z;
    A += (long)z * sA;  W += (long)z * sW;
    if (bias && bidx) bias += (long)bidx[z] * sBias;
    int row0 = blockIdx.y * 128, col0 = blockIdx.x * BN;
    int wm = wid & 3, wn = wid >> 2;

    float acc[2][NN][4];
#pragma unroll
    for (int i = 0; i < 2; i++)
#pragma unroll
        for (int j = 0; j < NN; j++)
#pragma unroll
            for (int q = 0; q < 4; q++) acc[i][j][q] = 0.f;

    auto loadStage = [&](int ch, int s) {
        int k0 = ch << 5;
        uint32_t sa = asb + s * ABYTES;
#pragma unroll
        for (int l = 0; l < 2; l++) {
            int idx = tid + l * 256;
            int r = idx >> 2, c = idx & 3;
            int gr = row0 + r;
            int grc = gr < M ? gr : M - 1;
            const __half* src = A + (long)grc * K3 + k0 + c * 8;
            uint32_t dst = sa + (uint32_t)(r * (SPITCH * 2) + c * 16);
            int bytes = (gr < M) ? 16 : 0;
            asm volatile("cp.async.cg.shared.global [%0], [%1], 16, %2;"
                :: "r"(dst), "l"(src), "r"(bytes));
        }
        uint32_t sb2 = bsb + s * BBYTES;
#pragma unroll
        for (int l = 0; l < LB; l++) {
            int idx = tid + l * 256;
            int r = idx >> 2, c = idx & 3;
            int gn = col0 + r;
            int gnc = gn < N ? gn : N - 1;
            const __half* src = W + (long)gnc * K3 + k0 + c * 8;
            uint32_t dst = sb2 + (uint32_t)(r * (SPITCH * 2) + c * 16);
            int bytes = (gn < N) ? 16 : 0;
            asm volatile("cp.async.cg.shared.global [%0], [%1], 16, %2;"
                :: "r"(dst), "l"(src), "r"(bytes));
        }
        asm volatile("cp.async.commit_group;" ::: "memory");
    };

    auto compute = [&](int s) {
        uint32_t a_base = asb + s * ABYTES
            + (uint32_t)((wm * 32 + (lane & 15)) * 80 + (lane >> 4) * 16);
        uint32_t b_base = bsb + s * BBYTES
            + (uint32_t)((wn * (BN / 2) + ((lane >> 4) & 1) * 8 + (lane & 7)) * 80
                         + ((lane >> 3) & 1) * 16);
#pragma unroll
        for (int ks = 0; ks < 2; ks++) {
            uint32_t a[2][4];
#pragma unroll
            for (int mm = 0; mm < 2; mm++) {
                uint32_t ad = a_base + (uint32_t)(mm * 16 * 80 + ks * 32);
                asm volatile("ldmatrix.sync.aligned.m8n8.x4.shared.b16 {%0,%1,%2,%3}, [%4];"
                    : "=r"(a[mm][0]), "=r"(a[mm][1]), "=r"(a[mm][2]), "=r"(a[mm][3])
                    : "r"(ad));
            }
            uint32_t b[NB][4];
#pragma unroll
            for (int nb = 0; nb < NB; nb++) {
                uint32_t bd = b_base + (uint32_t)(nb * 16 * 80 + ks * 32);
                asm volatile("ldmatrix.sync.aligned.m8n8.x4.shared.b16 {%0,%1,%2,%3}, [%4];"
                    : "=r"(b[nb][0]), "=r"(b[nb][1]), "=r"(b[nb][2]), "=r"(b[nb][3])
                    : "r"(bd));
            }
#pragma unroll
            for (int mm = 0; mm < 2; mm++)
#pragma unroll
                for (int nn = 0; nn < NN; nn++) {
                    uint32_t b0 = b[nn >> 1][(nn & 1) * 2];
                    uint32_t b1 = b[nn >> 1][(nn & 1) * 2 + 1];
                    asm volatile(
                        "mma.sync.aligned.m16n8k16.row.col.f32.f16.f16.f32 "
                        "{%0,%1,%2,%3}, {%4,%5,%6,%7}, {%8,%9}, {%0,%1,%2,%3};"
                        : "+f"(acc[mm][nn][0]), "+f"(acc[mm][nn][1]),
                          "+f"(acc[mm][nn][2]), "+f"(acc[mm][nn][3])
                        : "r"(a[mm][0]), "r"(a[mm][1]), "r"(a[mm][2]), "r"(a[mm][3]),
                          "r"(b0), "r"(b1));
                }
        }
    };

    int NC = K3 >> 5;
    loadStage(0, 0);
    loadStage(1, 1);
    for (int ch = 0; ch < NC; ch++) {
        // Final chunk has only ONE pending group -> must drain fully (race fix).
        if (ch + 1 < NC)
            asm volatile("cp.async.wait_group 1;" ::: "memory");
        else
            asm volatile("cp.async.wait_group 0;" ::: "memory");
        __syncthreads();
        // Issue next-next stage BEFORE compute (slot fenced by barrier above).
        int nx = ch + 2;
        if (nx < NC) loadStage(nx, nx % 3);
        compute(ch % 3);
    }

    float* Cf = (float*)Cv + (OSPLIT ? 0 : (long)z * sC);
    __half* Cb = (__half*)Cv + (OSPLIT ? (long)z * sC : 0);

    int g = lane >> 2, t = lane & 3;
#pragma unroll
    for (int mm = 0; mm < 2; mm++) {
#pragma unroll
        for (int half_ = 0; half_ < 2; half_++) {
            int gr = row0 + wm * 32 + mm * 16 + g + half_ * 8;
            if (gr >= M) continue;
#pragma unroll
            for (int nn = 0; nn < NN; nn++) {
                int gn = col0 + wn * (BN / 2) + nn * 8 + t * 2;
                float v0 = acc[mm][nn][half_ * 2];
                float v1 = acc[mm][nn][half_ * 2 + 1];
#pragma unroll
                for (int e = 0; e < 2; e++) {
                    int gnn = gn + e;
                    if (gnn >= N) continue;
                    float v = e ? v1 : v0;
                    if (bias) v += bias[gnn];
                    if (ACT == 1) v = v / (1.f + fabsf(v));
                    if (OSPLIT) {
                        __half hi, lo;
                        split3(v, hi, lo);
                        long base = (long)gr * ldc + 3L * gnn;
                        Cb[base] = hi; Cb[base + 1] = lo; Cb[base + 2] = hi;
                    } else {
                        long ci = (long)gr * ldc + gnn;
                        if (ACCUM) v += Cf[ci];
                        Cf[ci] = v;
                    }
                }
            }
        }
    }
}

// ---- fp32 -> 3-split fp16 conversions (2D grid, no div) ---------------------
// weights: [hi,hi,lo]
__global__ void cvt_w3(const float* __restrict__ W, __half* __restrict__ dst,
                       int K, int ldw, int K3P, int kh, long swh) {
    int n = blockIdx.y;
    int k = blockIdx.x * blockDim.x + threadIdx.x;
    int Kt = (K3P + 2) / 3;
    if (k >= Kt) return;
    float v = 0.f;
    if (k < K) {
        const float* Wp = W;
        int kk = k;
        if (kh && kk >= kh) { Wp += swh; kk -= kh; }
        v = Wp[(long)n * ldw + kk];
    }
    __half hi, lo;
    split3(v, hi, lo);
    long base = (long)n * K3P + 3L * k;
    dst[base] = hi;
    if (3L * k + 1 < K3P) dst[base + 1] = hi;
    if (3L * k + 2 < K3P) dst[base + 2] = lo;
}
// day weights, transposed read + day_idx gather
__global__ void cvt_w3_day(const float* __restrict__ day_w, const int* __restrict__ day_idx,
                           __half* __restrict__ dst) {
    int z = blockIdx.z;
    const float* W = day_w + (long)day_idx[z] * 512 * 512;
    int n = blockIdx.y;
    int k = blockIdx.x * blockDim.x + threadIdx.x;
    if (k >= 512) return;
    float v = W[(long)k * 512 + n];
    __half hi, lo;
    split3(v, hi, lo);
    long base = (long)z * 512 * K3P_IN + (long)n * K3P_IN + 3L * k;
    dst[base] = hi; dst[base + 1] = hi; dst[base + 2] = lo;
}
// activations: [hi,lo,hi]
__global__ void cvt_a3(const float* __restrict__ A, __half* __restrict__ dst,
                       int K, int lda, int K3P, long szA, long szD) {
    int z = blockIdx.z;
    A += (long)z * szA; dst += (long)z * szD;
    int r = blockIdx.y;
    int k = blockIdx.x * blockDim.x + threadIdx.x;
    int Kt = (K3P + 2) / 3;
    if (k >= Kt) return;
    float v = (k < K) ? A[(long)r * lda + k] : 0.f;
    __half hi, lo;
    split3(v, hi, lo);
    long base = (long)r * K3P + 3L * k;
    dst[base] = hi;
    if (3L * k + 1 < K3P) dst[base + 1] = lo;
    if (3L * k + 2 < K3P) dst[base + 2] = hi;
}

// ==================== f32x2 SIMT GEMM (classifier, exact fp32) ==============
__device__ __forceinline__ unsigned long long pack_dup(float a) {
    unsigned long long r;
    unsigned int au = __float_as_uint(a);
    asm("mov.b64 %0, {%1, %1};" : "=l"(r) : "r"(au));
    return r;
}
__device__ __forceinline__ void fma_x2(unsigned long long& acc,
                                       unsigned long long a, unsigned long long b) {
    asm("fma.rn.f32x2 %0, %1, %2, %0;" : "+l"(acc) : "l"(a), "l"(b));
}
__device__ __forceinline__ void unpack_x2(unsigned long long v, float& lo, float& hi) {
    unsigned int ul, uh;
    asm("mov.b64 {%0, %1}, %2;" : "=r"(ul), "=r"(uh) : "l"(v));
    lo = __uint_as_float(ul); hi = __uint_as_float(uh);
}

template<int BM, int BN, int TM, int TN>
__global__ __launch_bounds__((BM/TM)*(BN/TN))
void sgemm(const float* __restrict__ A, const float* __restrict__ W,
           const float* __restrict__ bias, float* __restrict__ C,
           int M, int N, int K, int lda, int ldw, int ldc)
{
    constexpr int NT = (BM/TM)*(BN/TN);
    constexpr int LA = BM*8/NT;
    constexpr int LB = BN*8/NT;
    constexpr int NX = BN/TN;

    __shared__ __align__(16) float As[8][BM];
    __shared__ __align__(16) float Bs[8][BN];

    int tid = threadIdx.x;
    int tx = tid % NX, ty = tid / NX;
    int row0 = blockIdx.y * BM, col0 = blockIdx.x * BN;

    unsigned long long acc[TM][TN/2];
#pragma unroll
    for (int i = 0; i < TM; i++)
#pragma unroll
        for (int j = 0; j < TN/2; j++) acc[i][j] = 0ull;

    float ra[LA], rb[LB];
    auto loadG = [&](int k0) {
#pragma unroll
        for (int l = 0; l < LA; l++) {
            int i = tid + l * NT;
            int r = i >> 3, c = i & 7;
            int gr = row0 + r, gk = k0 + c;
            ra[l] = (gr < M && gk < K) ? A[(long)gr * lda + gk] : 0.f;
        }
#pragma unroll
        for (int l = 0; l < LB; l++) {
            int i = tid + l * NT;
            int r = i >> 3, c = i & 7;
            int gn = col0 + r, gk = k0 + c;
            rb[l] = (gn < N && gk < K) ? W[(long)gn * ldw + gk] : 0.f;
        }
    };
    auto storeS = [&]() {
#pragma unroll
        for (int l = 0; l < LA; l++) {
            int i = tid + l * NT;
            As[i & 7][i >> 3] = ra[l];
        }
#pragma unroll
        for (int l = 0; l < LB; l++) {
            int i = tid + l * NT;
            Bs[i & 7][i >> 3] = rb[l];
        }
    };
    auto compute = [&]() {
#pragma unroll
        for (int kk = 0; kk < 8; kk++) {
            float a[TM];
            const float4* ap4 = reinterpret_cast<const float4*>(&As[kk][ty * TM]);
#pragma unroll
            for (int q = 0; q < TM/4; q++) {
                float4 tt = ap4[q];
                a[4*q+0] = tt.x; a[4*q+1] = tt.y; a[4*q+2] = tt.z; a[4*q+3] = tt.w;
            }
            unsigned long long bp[TN/2];
            const ulonglong2* bp2 = reinterpret_cast<const ulonglong2*>(&Bs[kk][tx * TN]);
#pragma unroll
            for (int q = 0; q < TN/4; q++) {
                ulonglong2 tt = bp2[q];
                bp[2*q] = tt.x; bp[2*q+1] = tt.y;
            }
#pragma unroll
            for (int i = 0; i < TM; i++) {
                unsigned long long ap = pack_dup(a[i]);
#pragma unroll
                for (int j = 0; j < TN/2; j++) fma_x2(acc[i][j], ap, bp[j]);
            }
        }
    };

    loadG(0);
    storeS();
    __syncthreads();
    for (int k0 = 8; k0 < K; k0 += 8) {
        loadG(k0);
        compute();
        __syncthreads();
        storeS();
        __syncthreads();
    }
    compute();

#pragma unroll
    for (int i = 0; i < TM; i++) {
        int gr = row0 + ty * TM + i;
        if (gr >= M) continue;
#pragma unroll
        for (int j = 0; j < TN/2; j++) {
            float v0, v1;
            unpack_x2(acc[i][j], v0, v1);
            int gn0 = col0 + tx * TN + 2*j;
#pragma unroll
            for (int e = 0; e < 2; e++) {
                int gn = gn0 + e;
                if (gn >= N) continue;
                float v = e ? v1 : v0;
                if (bias) v += bias[gn];
                C[(long)gr * ldc + gn] = v;
            }
        }
    }
}

// -------------------- pointwise kernels -------------------------------------
__global__ void copy_xt(const float* __restrict__ x) {
    int i = blockIdx.x * blockDim.x + threadIdx.x;
    if (i < BB * TT) g_h0[(long)i * DIN + (DIN - 1)] = x[(long)i * DIN + (DIN - 1)];
}

// layernorm fused with fp16 [hi,lo,hi] split -> g_a3 (in_proj input)
__global__ void ln_kernel(const float* __restrict__ w, const float* __restrict__ b) {
    int row = blockIdx.x;
    const float* xr = g_h + (long)row * DM;
    __half* orow = g_a3 + (long)row * K3P_IN;
    int tid = threadIdx.x;
    float v[4], s = 0.f, s2 = 0.f;
#pragma unroll
    for (int i = 0; i < 4; i++) { v[i] = xr[tid + i * 128]; s += v[i]; s2 += v[i] * v[i]; }
#pragma unroll
    for (int o = 16; o > 0; o >>= 1) {
        s  += __shfl_down_sync(0xffffffffu, s, o);
        s2 += __shfl_down_sync(0xffffffffu, s2, o);
    }
    __shared__ float sh[8];
    int wid = tid >> 5, lane = tid & 31;
    if (!lane) { sh[wid] = s; sh[4 + wid] = s2; }
    __syncthreads();
    if (tid == 0) {
        float ts = 0.f, t2 = 0.f;
        for (int i = 0; i < 4; i++) { ts += sh[i]; t2 += sh[4 + i]; }
        sh[0] = ts; sh[4] = t2;
    }
    __syncthreads();
    float mu = sh[0] / (float)DM;
    float var = sh[4] / (float)DM - mu * mu;
    float inv = rsqrtf(var + EPSF);
#pragma unroll
    for (int i = 0; i < 4; i++) {
        int c = tid + i * 128;
        float o = (v[i] - mu) * inv * w[c] + b[c];
        __half hi, lo;
        split3(o, hi, lo);
        orow[3*c] = hi; orow[3*c+1] = lo; orow[3*c+2] = hi;
    }
}

__global__ void conv_kernel(const float* __restrict__ conv_w,
                            const float* __restrict__ conv_b, int layer) {
    long idx = (long)blockIdx.x * blockDim.x + threadIdx.x;
    if (idx >= 2L * M2 * CONVD_) return;
    int c = (int)(idx % CONVD_);
    long r = idx / CONVD_;
    int dir = (int)(r / M2);
    int bt = (int)(r % M2);
    int b = bt / TO, t = bt % TO;
    int m = 2 * layer + dir;
    const float* wc = conv_w + ((long)m * CONVD_ + c) * DCONV;
    const float* zbase = g_zx + (long)dir * M2 * DINP + (long)b * TO * DINP;
    float s = conv_b[(long)m * CONVD_ + c];
#pragma unroll
    for (int j = 0; j < DCONV; j++) {
        int tt = dir ? (t + 3 - j) : (t - 3 + j);
        if (tt >= 0 && tt < TO) s += wc[j] * zbase[(long)tt * DINP + DI_ + c];
    }
    s = s / (1.f + expf(-s));
    g_xbc[(long)dir * M2 * CONVD_ + (long)bt * CONVD_ + c] = s;
}

__device__ __forceinline__ float softplusf(float x) {
    return x > 0.f ? x + log1pf(expf(-x)) : log1pf(expf(x));
}

// scan v3: grid (HH, BB, 2), 128 threads. Pair (p=tid>>1, g=tid&1): 32 states
// each, partial y combined via shfl_xor. All 4 SMSPs busy (vs 2 at 64 thr).
__global__ __launch_bounds__(128)
void scan_kernel(const float* __restrict__ Dp, const float* __restrict__ dtb,
                 const float* __restrict__ alog, int layer) {
    int h = blockIdx.x, b = blockIdx.y, dir = blockIdx.z;
    int m = 2 * layer + dir;
    int tid = threadIdx.x;
    int p = tid >> 1, g = tid & 1;
    float Dh = Dp[m * HH + h];
    float dtbias = dtb[m * HH + h];
    float Aneg = -expf(alog[m * HH + h]);

    __shared__ __align__(16) float sB[2][64], sC[2][64];

    float st[32];
#pragma unroll
    for (int i = 0; i < 32; i++) st[i] = 0.f;

    const float* xbase = g_xbc + (long)dir * M2 * CONVD_ + (long)b * TO * CONVD_;
    float*       ybase = g_y   + (long)dir * M2 * DI_    + (long)b * TO * DI_;
    const float* zbase = g_zx  + ((long)dir * M2 + (long)b * TO) * DINP + DI_ + CONVD_ + h;

    float rx, rBC, rraw;
    auto fetch = [&](int t) {
        const float* xr = xbase + (long)t * CONVD_;
        rx = xr[h * 64 + p];
        rBC = (tid < 64) ? xr[DI_ + tid] : xr[DI_ + DSTATE + (tid - 64)];
        rraw = zbase[(long)t * DINP];
    };
    fetch(dir ? (TO - 1) : 0);

    for (int s_ = 0; s_ < TO; s_++) {
        int buf = s_ & 1;
        int t = dir ? (TO - 1 - s_) : s_;
        if (tid < 64) sB[buf][tid] = rBC;
        else          sC[buf][tid - 64] = rBC;
        float xcur = rx, rawcur = rraw;
        __syncthreads();
        if (s_ + 1 < TO) fetch(dir ? (TO - 2 - s_) : (s_ + 1));

        float dt = softplusf(rawcur + dtbias);
        float da = expf(dt * Aneg);
        float dtx = dt * xcur;
        const float4* B4 = reinterpret_cast<const float4*>(&sB[buf][g * 32]);
        const float4* C4 = reinterpret_cast<const float4*>(&sC[buf][g * 32]);
        float ya = 0.f, yb = 0.f;
#pragma unroll
        for (int q = 0; q < 8; q++) {
            float4 bn = B4[q], cn = C4[q];
            float acc = 0.f;
            st[4*q+0] = st[4*q+0] * da + dtx * bn.x;  acc += st[4*q+0] * cn.x;
            st[4*q+1] = st[4*q+1] * da + dtx * bn.y;  acc += st[4*q+1] * cn.y;
            st[4*q+2] = st[4*q+2] * da + dtx * bn.z;  acc += st[4*q+2] * cn.z;
            st[4*q+3] = st[4*q+3] * da + dtx * bn.w;  acc += st[4*q+3] * cn.w;
            if (q < 4) ya += acc; else yb += acc;
        }
        float part = ya + yb;
        float oth = __shfl_xor_sync(0xffffffffu, part, 1);
        if (g == 0)
            ybase[(long)t * DI_ + h * 64 + p] = (part + oth) + Dh * xcur;
    }
}

// gated rmsnorm fused with split -> g_a3 row layout [row][ (dir*1024+c)*3 ]
__global__ void gnorm_kernel(const float* __restrict__ norm_w, int layer) {
    int row = blockIdx.x, dir = blockIdx.y;
    int m = 2 * layer + dir;
    const float* yrow = g_y + ((long)dir * M2 + row) * DI_;
    const float* zrow = g_zx + ((long)dir * M2 + row) * DINP;
    __half* orow = g_a3 + (long)row * K3P_OUT + (long)dir * (3 * DI_);
    int tid = threadIdx.x;
    float v[4], ss = 0.f;
#pragma unroll
    for (int i = 0; i < 4; i++) {
        int c = tid + i * 256;
        float z = zrow[c];
        float val = yrow[c] * (z / (1.f + expf(-z)));
        v[i] = val;
        ss += val * val;
    }
#pragma unroll
    for (int o = 16; o > 0; o >>= 1) ss += __shfl_down_sync(0xffffffffu, ss, o);
    __shared__ float sh[8];
    int wid = tid >> 5, lane = tid & 31;
    if (!lane) sh[wid] = ss;
    __syncthreads();
    if (tid == 0) { float tot = 0.f; for (int i = 0; i < 8; i++) tot += sh[i]; sh[0] = tot; }
    __syncthreads();
    float inv = rsqrtf(sh[0] / (float)DI_ + EPSF);
#pragma unroll
    for (int i = 0; i < 4; i++) {
        int c = tid + i * 256;
        float o = v[i] * inv * norm_w[(long)m * DI_ + c];
        __half hi, lo;
        split3(o, hi, lo);
        orow[3*c] = hi; orow[3*c+1] = lo; orow[3*c+2] = hi;
    }
}

// -------------------- host orchestration ------------------------------------
#define SMEM128 (STAGES * (128 + 128) * SPITCH * 2)   /* 61440 */
#define SMEM64  (STAGES * (128 + 64)  * SPITCH * 2)   /* 46080 */

extern "C" void kernel_launch(void* const* d_in, const int* in_sizes, int n_in,
                              void* d_out, int out_size) {
    const float* x        = (const float*)d_in[0];
    const int*   day_idx  = (const int*)  d_in[1];
    const float* day_w    = (const float*)d_in[2];
    const float* day_b    = (const float*)d_in[3];
    const float* w1       = (const float*)d_in[4];
    const float* b1       = (const float*)d_in[5];
    const float* w2       = (const float*)d_in[6];
    const float* b2       = (const float*)d_in[7];
    const float* ln_w     = (const float*)d_in[8];
    const float* ln_b     = (const float*)d_in[9];
    const float* m_in_w   = (const float*)d_in[10];
    const float* m_conv_w = (const float*)d_in[11];
    const float* m_conv_b = (const float*)d_in[12];
    const float* m_dt     = (const float*)d_in[13];
    const float* m_Alog   = (const float*)d_in[14];
    const float* m_D      = (const float*)d_in[15];
    const float* m_norm_w = (const float*)d_in[16];
    const float* m_out_w  = (const float*)d_in[17];
    const float* out_w    = (const float*)d_in[18];
    const float* out_b    = (const float*)d_in[19];
    float* out = (float*)d_out;

    float *h0, *h, *zx;
    __half *a3, *w3, *s3, *wm;
    cudaGetSymbolAddress((void**)&h0, g_h0);
    cudaGetSymbolAddress((void**)&h,  g_h);
    cudaGetSymbolAddress((void**)&zx, g_zx);
    cudaGetSymbolAddress((void**)&a3, g_a3);
    cudaGetSymbolAddress((void**)&w3, g_w3);
    cudaGetSymbolAddress((void**)&s3, g_s3);
    cudaGetSymbolAddress((void**)&wm, g_wm);
    __half* wm_out = wm + (size_t)10 * DINP * K3P_IN;

    cudaFuncSetAttribute(mma_gemm<128,1,0,0>, cudaFuncAttributeMaxDynamicSharedMemorySize, SMEM128);
    cudaFuncSetAttribute(mma_gemm<128,1,0,1>, cudaFuncAttributeMaxDynamicSharedMemorySize, SMEM128);
    cudaFuncSetAttribute(mma_gemm<128,0,0,0>, cudaFuncAttributeMaxDynamicSharedMemorySize, SMEM128);
    cudaFuncSetAttribute(mma_gemm<64,0,0,0>,  cudaFuncAttributeMaxDynamicSharedMemorySize, SMEM64);
    cudaFuncSetAttribute(mma_gemm<64,0,1,0>,  cudaFuncAttributeMaxDynamicSharedMemorySize, SMEM64);

    // 0. hoisted weight conversions (constant w.r.t. activations)
    cvt_w3<<<dim3(2, 10 * DINP, 1), 256>>>(m_in_w, wm, DM, DM, K3P_IN, 0, 0);
    for (int i = 0; i < LL; i++)
        cvt_w3<<<dim3(8, DM, 1), 256>>>(
            m_out_w + (long)(2 * i) * DM * DI_, wm_out + (long)i * DM * K3P_OUT,
            2 * DI_, DI_, K3P_OUT, DI_, (long)DM * DI_);

    // 1. day transform via mma (softsign, per-batch gathered weight+bias)
    cvt_w3_day<<<dim3(2, 512, BB), 256>>>(day_w, day_idx, s3);
    cvt_a3<<<dim3(2, TT, BB), 256>>>(x, a3, 512, DIN, K3P_IN,
                                     (long)TT * DIN, (long)TT * K3P_IN);
    mma_gemm<128,1,0,0><<<dim3(4, 16, BB), 256, SMEM128>>>(
        a3, s3, day_b, (void*)h0, TT, 512, K3P_IN, DIN,
        (long)TT * K3P_IN, 512L * K3P_IN, (long)TT * DIN, day_idx, 512);

    // 2. passthrough last channel
    copy_xt<<<(BB * TT + 255) / 256, 256>>>(x);

    // 3. w1 patch projection; epilogue writes split fp16 into g_s3 (w2 input)
    cvt_w3<<<dim3(29, PROJD, 1), 256>>>(w1, w3, 7182, 7182, K3P_W1, 0, 0);
    cvt_a3<<<dim3(29, TO, BB), 256>>>(h0, a3, 7182, 4 * DIN, K3P_W1,
                                      (long)TT * DIN, (long)TO * K3P_W1);
    mma_gemm<128,1,0,1><<<dim3(PROJD / 128, 4, BB), 256, SMEM128>>>(
        a3, w3, b1, (void*)s3, TO, PROJD, K3P_W1, K3P_W2,
        (long)TO * K3P_W1, 0, (long)TO * K3P_W2, nullptr, 0);

    // 4. w2: reads split fp16 from g_s3, writes fp32 h
    cvt_w3<<<dim3(16, DM, 1), 256>>>(w2, w3, PROJD, PROJD, K3P_W2, 0, 0);
    mma_gemm<64,0,0,0><<<dim3(DM / 64, 16, 1), 256, SMEM64>>>(
        s3, w3, b2, (void*)h, M2, DM, K3P_W2, DM, 0, 0, 0, nullptr, 0);

    // 5. layers
    for (int i = 0; i < LL; i++) {
        ln_kernel<<<M2, 128>>>(ln_w + (long)i * DM, ln_b + (long)i * DM);

        mma_gemm<128,0,0,0><<<dim3((DINP + 127) / 128, 16, 2), 256, SMEM128>>>(
            a3, wm + (long)(2 * i) * DINP * K3P_IN, nullptr, (void*)zx,
            M2, DINP, K3P_IN, DINP,
            0, (long)DINP * K3P_IN, (long)M2 * DINP, nullptr, 0);

        conv_kernel<<<(int)((2L * M2 * CONVD_ + 255) / 256), 256>>>(m_conv_w, m_conv_b, i);
        scan_kernel<<<dim3(HH, BB, 2), 128>>>(m_D, m_dt, m_Alog, i);
        gnorm_kernel<<<dim3(M2, 2), 256>>>(m_norm_w, i);

        mma_gemm<64,0,1,0><<<dim3(DM / 64, 16, 1), 256, SMEM64>>>(
            a3, wm_out + (long)i * DM * K3P_OUT, nullptr, (void*)h,
            M2, DM, K3P_OUT, DM, 0, 0, 0, nullptr, 0);
    }

    // 6. classifier (small; f32x2 SIMT)
    sgemm<64,64,4,4><<<dim3(1, (M2 + 63) / 64, 1), 256>>>(
        h, out_w, out_b, out, M2, 41, DM, DM, DM, 41);
}